// round 2
// baseline (speedup 1.0000x reference)
#include <cuda_runtime.h>
#include <cstdint>

#define NN 100000
#define NE 3200000
#define NG 64
#define SCAN_CHUNK 4096
#define NB_SCAN ((NN + SCAN_CHUNK - 1) / SCAN_CHUNK)  // 25

// ---------------- scratch (static device globals; no allocation) ----------------
__device__ float g_dinv[NN];
__device__ int   g_row_ptr[NN + 1];
__device__ int   g_cur[NN];            // histogram, then fill cursor
__device__ int   g_partials[64];
__device__ float2 g_edge[NE];          // .x = src (bits), .y = ew -> norm (in place)
__device__ float g_agg1[NN * 16];
__device__ float g_h1[NN * 16];
__device__ float g_agg2[NN * 16];
__device__ float g_h2[NN * 64];
__device__ float g_agg3[NN * 64];
__device__ float g_sums[NG * 256];
__device__ float g_cnt[NG];

__device__ __forceinline__ float silu(float v) { return v / (1.0f + __expf(-v)); }

__device__ __forceinline__ void redAdd4(float* addr, float a, float b, float c, float d) {
    asm volatile("red.global.add.v4.f32 [%0], {%1,%2,%3,%4};"
                 :: "l"(addr), "f"(a), "f"(b), "f"(c), "f"(d) : "memory");
}

#define FMA2(d, a, b) asm("fma.rn.f32x2 %0, %1, %2, %0;" : "+l"(d) : "l"(a), "l"(b))

// ---------------- CSR build ----------------
__global__ void k_zero(int* cur, float* sums, float* cnt, int n) {
    int i = blockIdx.x * blockDim.x + threadIdx.x;
    if (i < n) cur[i] = 0;
    if (i < NG * 256) sums[i] = 0.f;
    if (i < NG) cnt[i] = 0.f;
}

__global__ void k_hist(const int* __restrict__ dst, int* cur, int e) {
    int i = blockIdx.x * blockDim.x + threadIdx.x;
    if (i < e) atomicAdd(&cur[dst[i]], 1);
}

__global__ void k_scan1(const int* __restrict__ cnt, int* row_ptr, int* partials, int n) {
    __shared__ int sh[1024];
    int t = threadIdx.x;
    int base = blockIdx.x * SCAN_CHUNK + t * 4;
    int v[4];
    int s = 0;
#pragma unroll
    for (int k = 0; k < 4; k++) {
        int i = base + k;
        v[k] = (i < n) ? cnt[i] : 0;
        s += v[k];
    }
    sh[t] = s;
    __syncthreads();
    for (int off = 1; off < 1024; off <<= 1) {
        int x = (t >= off) ? sh[t - off] : 0;
        __syncthreads();
        sh[t] += x;
        __syncthreads();
    }
    int excl = sh[t] - s;
#pragma unroll
    for (int k = 0; k < 4; k++) {
        int i = base + k;
        if (i < n) row_ptr[i] = excl;
        excl += v[k];
    }
    if (t == 1023) partials[blockIdx.x] = sh[1023];
}

__global__ void k_scan2(int* partials, int nb, int* row_ptr, int n, int e) {
    int run = 0;
    for (int b = 0; b < nb; b++) {
        int t = partials[b];
        partials[b] = run;
        run += t;
    }
    row_ptr[n] = e;
}

__global__ void k_scan3(int* row_ptr, int* cur, const int* __restrict__ partials, int n) {
    int i = blockIdx.x * blockDim.x + threadIdx.x;
    if (i >= n) return;
    int r = row_ptr[i] + partials[i / SCAN_CHUNK];
    row_ptr[i] = r;
    cur[i] = r;
}

__global__ void k_fill(const int* __restrict__ src, const int* __restrict__ dst,
                       const float* __restrict__ ew, int* cur, float2* edge, int e) {
    int i = blockIdx.x * blockDim.x + threadIdx.x;
    if (i >= e) return;
    int d = dst[i];
    int p = atomicAdd(&cur[d], 1);
    float2 rec;
    rec.x = __int_as_float(src[i]);
    rec.y = ew[i];
    edge[p] = rec;
}

// deg_i = 1 + sum_e ew ; dinv = rsqrt(deg). One warp per node.
__global__ void k_deg(const int* __restrict__ row_ptr, const float2* __restrict__ edge,
                      float* dinv, int n) {
    int w = (blockIdx.x * blockDim.x + threadIdx.x) >> 5;
    int lane = threadIdx.x & 31;
    if (w >= n) return;
    int s = row_ptr[w], eN = row_ptr[w + 1];
    float sum = 0.f;
    for (int e = s + lane; e < eN; e += 32) sum += edge[e].y;
#pragma unroll
    for (int off = 16; off; off >>= 1) sum += __shfl_xor_sync(0xffffffffu, sum, off);
    if (lane == 0) dinv[w] = rsqrtf(1.0f + sum);
}

// edge.y <- dinv[dst] * ew * dinv[src]  (in place). One warp per node.
__global__ void k_normize(const int* __restrict__ row_ptr, float2* edge,
                          const float* __restrict__ dinv, int n) {
    int w = (blockIdx.x * blockDim.x + threadIdx.x) >> 5;
    int lane = threadIdx.x & 31;
    if (w >= n) return;
    int s = row_ptr[w], eN = row_ptr[w + 1];
    float dn = __ldg(&dinv[w]);
    for (int e = s + lane; e < eN; e += 32) {
        float2 r = edge[e];
        int sn = __float_as_int(r.x);
        r.y = dn * r.y * __ldg(&dinv[sn]);
        edge[e] = r;
    }
}

// ---------------- aggregation (gather-only) ----------------
// dim 16: 16 lanes per node (2 nodes per warp), 1 float per lane.
__global__ void k_agg16(const int* __restrict__ row_ptr, const float2* __restrict__ edge,
                        const float* __restrict__ h, const float* __restrict__ dinv,
                        float* __restrict__ agg, int n) {
    int tid = blockIdx.x * blockDim.x + threadIdx.x;
    int node = tid >> 4;
    int lane = tid & 15;
    if (node >= n) return;
    int s = row_ptr[node], eN = row_ptr[node + 1];
    float d = dinv[node];
    float acc0 = h[(size_t)node * 16 + lane] * d * d;
    float acc1 = 0.f;
    int e = s;
    for (; e + 1 < eN; e += 2) {
        float2 r0 = edge[e];
        float2 r1 = edge[e + 1];
        int s0 = __float_as_int(r0.x);
        int s1 = __float_as_int(r1.x);
        float v0 = h[(size_t)s0 * 16 + lane];
        float v1 = h[(size_t)s1 * 16 + lane];
        acc0 += r0.y * v0;
        acc1 += r1.y * v1;
    }
    if (e < eN) {
        float2 r = edge[e];
        int sn = __float_as_int(r.x);
        acc0 += r.y * h[(size_t)sn * 16 + lane];
    }
    agg[(size_t)node * 16 + lane] = acc0 + acc1;
}

// dim 64: one warp per node, float2 per lane.
__global__ void k_agg64(const int* __restrict__ row_ptr, const float2* __restrict__ edge,
                        const float* __restrict__ h, const float* __restrict__ dinv,
                        float* __restrict__ agg, int n) {
    int node = (blockIdx.x * blockDim.x + threadIdx.x) >> 5;
    int lane = threadIdx.x & 31;
    if (node >= n) return;
    int s = row_ptr[node], eN = row_ptr[node + 1];
    const float2* H = (const float2*)h;
    float d = dinv[node];
    float d2 = d * d;
    float2 acc0 = H[(size_t)node * 32 + lane];
    acc0.x *= d2;
    acc0.y *= d2;
    float2 acc1 = make_float2(0.f, 0.f);
    int e = s;
    for (; e + 1 < eN; e += 2) {
        float2 r0 = edge[e];
        float2 r1 = edge[e + 1];
        int s0 = __float_as_int(r0.x);
        int s1 = __float_as_int(r1.x);
        float2 v0 = H[(size_t)s0 * 32 + lane];
        float2 v1 = H[(size_t)s1 * 32 + lane];
        acc0.x += r0.y * v0.x;
        acc0.y += r0.y * v0.y;
        acc1.x += r1.y * v1.x;
        acc1.y += r1.y * v1.y;
    }
    if (e < eN) {
        float2 r = edge[e];
        int sn = __float_as_int(r.x);
        float2 v = H[(size_t)sn * 32 + lane];
        acc0.x += r.y * v.x;
        acc0.y += r.y * v.y;
    }
    acc0.x += acc1.x;
    acc0.y += acc1.y;
    ((float2*)agg)[(size_t)node * 32 + lane] = acc0;
}

// ---------------- transforms ----------------
// DIN=16, DOUT in {16,64}. One thread per node, W in smem, fully unrolled.
template <int DOUT>
__global__ void k_transform16(const float* __restrict__ agg, const float* __restrict__ W,
                              const float* __restrict__ b, float* __restrict__ hout, int n) {
    __shared__ float4 sW4[16 * DOUT / 4];
    __shared__ float sB[DOUT];
    int tid = threadIdx.x;
    for (int k = tid; k < 16 * DOUT / 4; k += blockDim.x) sW4[k] = ((const float4*)W)[k];
    for (int k = tid; k < DOUT; k += blockDim.x) sB[k] = b[k];
    __syncthreads();
    int node = blockIdx.x * blockDim.x + tid;
    if (node >= n) return;

    const float4* A4 = (const float4*)(agg + (size_t)node * 16);
    float4 a0 = A4[0], a1 = A4[1], a2 = A4[2], a3 = A4[3];
    float av[16] = {a0.x, a0.y, a0.z, a0.w, a1.x, a1.y, a1.z, a1.w,
                    a2.x, a2.y, a2.z, a2.w, a3.x, a3.y, a3.z, a3.w};

    float4 acc[DOUT / 4];
#pragma unroll
    for (int k = 0; k < DOUT / 4; k++) acc[k] = make_float4(0.f, 0.f, 0.f, 0.f);
#pragma unroll
    for (int i = 0; i < 16; i++) {
#pragma unroll
        for (int k = 0; k < DOUT / 4; k++) {
            float4 w = sW4[i * (DOUT / 4) + k];
            acc[k].x += av[i] * w.x;
            acc[k].y += av[i] * w.y;
            acc[k].z += av[i] * w.z;
            acc[k].w += av[i] * w.w;
        }
    }
    float4* H4 = (float4*)(hout + (size_t)node * DOUT);
#pragma unroll
    for (int k = 0; k < DOUT / 4; k++) {
        float4 v;
        v.x = silu(acc[k].x + sB[4 * k + 0]);
        v.y = silu(acc[k].y + sB[4 * k + 1]);
        v.z = silu(acc[k].z + sB[4 * k + 2]);
        v.w = silu(acc[k].w + sB[4 * k + 3]);
        H4[k] = v;
    }
}

// DIN=64, DOUT=256, fused mean-pool accumulation (sums[batch[node]] += silu(...)).
// Block = 256 threads = 8 warps, 4 nodes/warp -> 32 nodes/block. f32x2 packed FMA.
__global__ void k_transform64_256_pool(const float* __restrict__ agg,
                                       const float* __restrict__ W,
                                       const float* __restrict__ b,
                                       const int* __restrict__ batch,
                                       float* __restrict__ sums, int n) {
    extern __shared__ float smem[];
    float* sW = smem;             // 64*256
    float* sA = smem + 64 * 256;  // 32*64
    int tid = threadIdx.x;
    int lane = tid & 31;
    int warp = tid >> 5;
    int nodeBase = blockIdx.x * 32;

    const float4* W4 = (const float4*)W;
    float4* sW4 = (float4*)sW;
#pragma unroll
    for (int k = 0; k < 16; k++) sW4[tid + k * 256] = W4[tid + k * 256];
    const float4* A4 = (const float4*)(agg + (size_t)nodeBase * 64);
    float4* sA4 = (float4*)sA;
#pragma unroll
    for (int k = 0; k < 2; k++) sA4[tid + k * 256] = A4[tid + k * 256];
    __syncthreads();

    unsigned long long acc[4][4];
#pragma unroll
    for (int j = 0; j < 4; j++)
#pragma unroll
        for (int k = 0; k < 4; k++) acc[j][k] = 0ull;

    int o0 = lane * 8;
#pragma unroll 8
    for (int i = 0; i < 64; i++) {
        ulonglong2 wa = *(const ulonglong2*)&sW[i * 256 + o0];
        ulonglong2 wb = *(const ulonglong2*)&sW[i * 256 + o0 + 4];
#pragma unroll
        for (int j = 0; j < 4; j++) {
            float a = sA[(warp * 4 + j) * 64 + i];
            unsigned long long ap;
            asm("mov.b64 %0, {%1, %1};" : "=l"(ap) : "f"(a));
            FMA2(acc[j][0], ap, wa.x);
            FMA2(acc[j][1], ap, wa.y);
            FMA2(acc[j][2], ap, wb.x);
            FMA2(acc[j][3], ap, wb.y);
        }
    }

    float bb[8];
#pragma unroll
    for (int k = 0; k < 8; k++) bb[k] = __ldg(&b[o0 + k]);

#pragma unroll
    for (int j = 0; j < 4; j++) {
        int node = nodeBase + warp * 4 + j;
        if (node >= n) continue;
        float v[8];
#pragma unroll
        for (int k = 0; k < 4; k++) {
            float lo, hi;
            asm("mov.b64 {%0, %1}, %2;" : "=f"(lo), "=f"(hi) : "l"(acc[j][k]));
            v[2 * k] = lo;
            v[2 * k + 1] = hi;
        }
#pragma unroll
        for (int k = 0; k < 8; k++) v[k] = silu(v[k] + bb[k]);
        int g = __ldg(&batch[node]);
        float* base = sums + (size_t)g * 256 + o0;
        redAdd4(base, v[0], v[1], v[2], v[3]);
        redAdd4(base + 4, v[4], v[5], v[6], v[7]);
    }
}

// ---------------- cnt + MLP head ----------------
__global__ void k_cnt(const int* __restrict__ batch, float* cnt, int n) {
    int i = blockIdx.x * blockDim.x + threadIdx.x;
    if (i < n) atomicAdd(&cnt[batch[i]], 1.0f);
}

__global__ void k_mlp(const float* __restrict__ sums, const float* __restrict__ cnt,
                      const float* __restrict__ L1, const float* __restrict__ c1,
                      const float* __restrict__ L2, const float* __restrict__ c2,
                      const float* __restrict__ L3, const float* __restrict__ c3,
                      float* __restrict__ out) {
    __shared__ float sp[256];
    __shared__ float s1[128];
    __shared__ float s2[64];
    int g = blockIdx.x;
    int t = threadIdx.x;  // 128
    float invc = 1.0f / fmaxf(cnt[g], 1.0f);
    sp[t] = sums[g * 256 + t] * invc;
    sp[t + 128] = sums[g * 256 + 128 + t] * invc;
    __syncthreads();
    {
        float acc = c1[t];
        for (int i = 0; i < 256; i++) acc += sp[i] * L1[i * 128 + t];
        s1[t] = silu(acc);
    }
    __syncthreads();
    if (t < 64) {
        float acc = c2[t];
        for (int i = 0; i < 128; i++) acc += s1[i] * L2[i * 64 + t];
        s2[t] = silu(acc);
    }
    __syncthreads();
    if (t < 3) {
        float acc = c3[t];
        for (int i = 0; i < 64; i++) acc += s2[i] * L3[i * 3 + t];
        out[g * 3 + t] = acc;
    }
}

// ---------------- launch ----------------
static void* sym(const void* s) {
    void* p = nullptr;
    cudaGetSymbolAddress(&p, s);
    return p;
}

extern "C" void kernel_launch(void* const* d_in, const int* in_sizes, int n_in,
                              void* d_out, int out_size) {
    const float* x = (const float*)d_in[0];
    const int* ei = (const int*)d_in[1];
    const float* ew = (const float*)d_in[2];
    const int* batch = (const int*)d_in[3];
    const float* W1 = (const float*)d_in[4];
    const float* b1 = (const float*)d_in[5];
    const float* W2 = (const float*)d_in[6];
    const float* b2 = (const float*)d_in[7];
    const float* W3 = (const float*)d_in[8];
    const float* b3 = (const float*)d_in[9];
    const float* L1 = (const float*)d_in[10];
    const float* c1 = (const float*)d_in[11];
    const float* L2 = (const float*)d_in[12];
    const float* c2 = (const float*)d_in[13];
    const float* L3 = (const float*)d_in[14];
    const float* c3 = (const float*)d_in[15];
    float* out = (float*)d_out;

    const int N = in_sizes[0] / 16;  // 100000
    const int E = in_sizes[2];       // 3200000
    const int* src = ei;
    const int* dst = ei + E;

    float* dinv = (float*)sym(g_dinv);
    int* row_ptr = (int*)sym(g_row_ptr);
    int* cur = (int*)sym(g_cur);
    int* partials = (int*)sym(g_partials);
    float2* edge = (float2*)sym(g_edge);
    float* agg1 = (float*)sym(g_agg1);
    float* h1 = (float*)sym(g_h1);
    float* agg2 = (float*)sym(g_agg2);
    float* h2 = (float*)sym(g_h2);
    float* agg3 = (float*)sym(g_agg3);
    float* sums = (float*)sym(g_sums);
    float* cnt = (float*)sym(g_cnt);

    const int T = 256;
    int gn = (N + T - 1) / T;
    int ge = (E + T - 1) / T;
    int gw = (N * 32 + T - 1) / T;   // warp per node
    int gh = (N * 16 + T - 1) / T;   // 16 lanes per node

    // CSR build
    k_zero<<<gn, T>>>(cur, sums, cnt, N);
    k_hist<<<ge, T>>>(dst, cur, E);
    k_scan1<<<NB_SCAN, 1024>>>(cur, row_ptr, partials, N);
    k_scan2<<<1, 1>>>(partials, NB_SCAN, row_ptr, N, E);
    k_scan3<<<gn, T>>>(row_ptr, cur, partials, N);
    k_fill<<<ge, T>>>(src, dst, ew, cur, edge, E);

    // degree / norm
    k_deg<<<gw, T>>>(row_ptr, edge, dinv, N);
    k_normize<<<gw, T>>>(row_ptr, edge, dinv, N);

    // layer 1 (16 -> 16)
    k_agg16<<<gh, T>>>(row_ptr, edge, x, dinv, agg1, N);
    k_transform16<16><<<gn, T>>>(agg1, W1, b1, h1, N);

    // layer 2 (16 -> 64)
    k_agg16<<<gh, T>>>(row_ptr, edge, h1, dinv, agg2, N);
    k_transform16<64><<<gn, T>>>(agg2, W2, b2, h2, N);

    // layer 3 (64 -> 256) + fused pool
    k_agg64<<<gw, T>>>(row_ptr, edge, h2, dinv, agg3, N);
    k_cnt<<<gn, T>>>(batch, cnt, N);
    {
        int smemBytes = (64 * 256 + 32 * 64) * (int)sizeof(float);  // 72KB
        cudaFuncSetAttribute(k_transform64_256_pool,
                             cudaFuncAttributeMaxDynamicSharedMemorySize, smemBytes);
        int blocks = (N + 31) / 32;
        k_transform64_256_pool<<<blocks, 256, smemBytes>>>(agg3, W3, b3, batch, sums, N);
    }

    // MLP head
    k_mlp<<<NG, 128>>>(sums, cnt, L1, c1, L2, c2, L3, c3, out);
}